// round 1
// baseline (speedup 1.0000x reference)
#include <cuda_runtime.h>

#define Bdim 128
#define Ndim 2048
#define Ddim 128
#define HOPS 3
#define CH 256   // n-chunk per k_attn block

// ---- scratch (allocation-free: device globals) ----
__device__ float g_fscore[Bdim * Ndim];   // mask * (value . w_f)
__device__ float g_u[Bdim * Ddim];        // current u (hops 1,2 input)
__device__ float g_ubatch[Bdim * Ddim];   // relu(u @ W^T + b)
__device__ float g_o[Bdim * Ddim];        // attention output accumulator
__device__ float g_scal[Bdim * 4];        // per-b: [0]=s+c, [1]=M, [2]=1/denom

// ============================================================
// Pass 1 (once): fscore[b,n] = mask[b,n] * sum_d value[b,n,d]*w_f[d]
// One warp per (b,n) row. Skip the 134MB read where mask==0.
// ============================================================
__global__ void k_fscore(const float* __restrict__ value,
                         const float* __restrict__ mask,
                         const float* __restrict__ attfc_w) {
    int warp = (blockIdx.x * blockDim.x + threadIdx.x) >> 5;
    int lane = threadIdx.x & 31;
    if (warp >= Bdim * Ndim) return;

    float m = mask[warp];                      // broadcast load
    if (m == 0.0f) {
        if (lane == 0) g_fscore[warp] = 0.0f;
        return;
    }
    const float4* vp = (const float4*)(value + (size_t)warp * Ddim);
    float4 v = vp[lane];
    float4 w = ((const float4*)attfc_w)[lane];  // w_f = attfc_w[0 .. D)
    float s = v.x * w.x + v.y * w.y + v.z * w.z + v.w * w.w;
    #pragma unroll
    for (int off = 16; off; off >>= 1)
        s += __shfl_down_sync(0xffffffffu, s, off);
    if (lane == 0) g_fscore[warp] = m * s;
}

// ============================================================
// Per-hop prep (one block per b, 128 threads):
//   u_batch = relu(u @ linfc_w^T + linfc_b)
//   s  = u . w_u ;  sc = s + attfc_b
//   M  = relu(max_n (fscore + sc))      (relu monotone => = max att)
//   denom = sum_n mask * exp(relu(fscore+sc) - M) + 1e-5
// Also zeroes g_o for this b.
// ============================================================
__global__ void k_prep(const float* __restrict__ u_in, int use_gu,
                       const float* __restrict__ linfc_w,
                       const float* __restrict__ linfc_b,
                       const float* __restrict__ attfc_w,
                       const float* __restrict__ attfc_b,
                       const float* __restrict__ mask) {
    int b = blockIdx.x;
    int t = threadIdx.x;
    __shared__ float u_sh[Ddim];
    __shared__ float red[128];

    const float* up = use_gu ? (const float*)g_u : u_in;
    u_sh[t] = up[b * Ddim + t];
    __syncthreads();

    // u_batch row (thread t -> output feature t)
    float acc = linfc_b[t];
    const float* wrow = linfc_w + t * Ddim;
    #pragma unroll 8
    for (int k = 0; k < Ddim; k++) acc = fmaf(u_sh[k], __ldg(wrow + k), acc);
    g_ubatch[b * Ddim + t] = fmaxf(acc, 0.0f);
    g_o[b * Ddim + t] = 0.0f;

    // s = u . w_u  (w_u = attfc_w[D .. 2D))
    red[t] = u_sh[t] * attfc_w[Ddim + t];
    __syncthreads();
    #pragma unroll
    for (int off = 64; off; off >>= 1) {
        if (t < off) red[t] += red[t + off];
        __syncthreads();
    }
    float sc = red[0] + attfc_b[0];
    __syncthreads();

    // max over v = fscore + sc
    float mx = -1e30f;
    for (int n = t; n < Ndim; n += 128)
        mx = fmaxf(mx, g_fscore[b * Ndim + n]);
    red[t] = mx;
    __syncthreads();
    #pragma unroll
    for (int off = 64; off; off >>= 1) {
        if (t < off) red[t] = fmaxf(red[t], red[t + off]);
        __syncthreads();
    }
    float M = fmaxf(red[0] + sc, 0.0f);
    __syncthreads();

    // denom
    float ds = 0.0f;
    for (int n = t; n < Ndim; n += 128) {
        float v = fmaxf(g_fscore[b * Ndim + n] + sc, 0.0f);
        ds += mask[b * Ndim + n] * __expf(v - M);
    }
    red[t] = ds;
    __syncthreads();
    #pragma unroll
    for (int off = 64; off; off >>= 1) {
        if (t < off) red[t] += red[t + off];
        __syncthreads();
    }
    if (t == 0) {
        g_scal[b * 4 + 0] = sc;
        g_scal[b * 4 + 1] = M;
        g_scal[b * 4 + 2] = 1.0f / (red[0] + 1e-5f);
    }
}

// ============================================================
// Per-hop big pass: o[b,d] += sum_{n in chunk} w[n] * value[b,n,d]
//   w[n] = exp(relu(fscore+sc) - M) * mask * inv_denom
// (mask^2 == mask since mask in {0,1}, so one factor suffices.)
// Skip rows with w==0 (warp-uniform) -> ~30% HBM traffic saved.
// ============================================================
__global__ void k_attn(const float* __restrict__ value,
                       const float* __restrict__ mask) {
    int b  = blockIdx.x;
    int n0 = blockIdx.y * CH;
    int t  = threadIdx.x;
    __shared__ float w_sh[CH];

    float sc   = g_scal[b * 4 + 0];
    float M    = g_scal[b * 4 + 1];
    float invd = g_scal[b * 4 + 2];

    for (int i = t; i < CH; i += 128) {
        int n = n0 + i;
        float mk = mask[b * Ndim + n];
        float v  = fmaxf(g_fscore[b * Ndim + n] + sc, 0.0f);
        w_sh[i] = mk * __expf(v - M) * invd;
    }
    __syncthreads();

    float acc = 0.0f;
    const float* vp = value + ((size_t)b * Ndim + n0) * Ddim + t;
    #pragma unroll 4
    for (int j = 0; j < CH; j++) {
        float w = w_sh[j];
        if (w != 0.0f) acc = fmaf(w, __ldg(vp + (size_t)j * Ddim), acc);
    }
    atomicAdd(&g_o[b * Ddim + t], acc);
}

// ============================================================
// u_new = u_batch + o ; write g_u (and d_out on last hop)
// ============================================================
__global__ void k_update(float* __restrict__ out, int write_out) {
    int i = blockIdx.x * 128 + threadIdx.x;
    float r = g_ubatch[i] + g_o[i];
    g_u[i] = r;
    if (write_out) out[i] = r;
}

// ============================================================
extern "C" void kernel_launch(void* const* d_in, const int* in_sizes, int n_in,
                              void* d_out, int out_size) {
    const float* e1    = (const float*)d_in[0];
    // d_in[1] rel_embeded   : unused by reference
    // d_in[2] nei_embeded_key: unused by reference
    const float* value = (const float*)d_in[3];
    const float* mask  = (const float*)d_in[4];
    const float* lw    = (const float*)d_in[5];
    const float* lb    = (const float*)d_in[6];
    const float* aw    = (const float*)d_in[7];
    const float* ab    = (const float*)d_in[8];
    float* out = (float*)d_out;

    // fscore once (hop-invariant)
    k_fscore<<<(Bdim * Ndim) / 8, 256>>>(value, mask, aw);

    for (int h = 0; h < HOPS; h++) {
        k_prep<<<Bdim, 128>>>(e1, h > 0 ? 1 : 0, lw, lb, aw, ab, mask);
        dim3 g2(Bdim, Ndim / CH);
        k_attn<<<g2, 128>>>(value, mask);
        k_update<<<Bdim, 128>>>(out, h == HOPS - 1 ? 1 : 0);
    }
}

// round 2
// speedup vs baseline: 2.1429x; 2.1429x over previous
#include <cuda_runtime.h>

#define Bdim 128
#define Ndim 2048
#define Ddim 128
#define CH 256          // rows per k_attn block

// ---- scratch (allocation-free device globals) ----
__device__ float g_f[Bdim * Ndim];    // masked f_n = mask * (v . w_f)
__device__ float g_g[Bdim * Ndim];    // masked g_n = mask * (v . w_u)
__device__ float g_ub0[Bdim * Ddim];  // relu(W e1 + b)
__device__ float g_o0[Bdim * Ddim];
__device__ float g_o1[Bdim * Ddim];
__device__ float g_scal[Bdim * 16];   // [0]sc0 [1]M0 [2]inv0 [3]sc1 [4]M1 [5]inv1
                                      // [6]sc2 [7]M2 [8]inv2 [9]maxf

// ---------- block reduction helpers (256 threads) ----------
__device__ __forceinline__ float blk_sum(float v, float* red, int t) {
    red[t] = v; __syncthreads();
    #pragma unroll
    for (int off = 128; off; off >>= 1) {
        if (t < off) red[t] += red[t + off];
        __syncthreads();
    }
    float r = red[0]; __syncthreads();
    return r;
}
__device__ __forceinline__ float blk_max(float v, float* red, int t) {
    red[t] = v; __syncthreads();
    #pragma unroll
    for (int off = 128; off; off >>= 1) {
        if (t < off) red[t] = fmaxf(red[t], red[t + off]);
        __syncthreads();
    }
    float r = red[0]; __syncthreads();
    return r;
}

// ============================================================
// Pass 1 (once): f = mask*(v.w_f), g = mask*(v.w_u)
// 8 warps/block, 4 rows/warp (4 LDG.128 in flight), combined
// f/g butterfly reduction (6 shuffles per row).
// ============================================================
__global__ __launch_bounds__(256) void k_pass1(
        const float* __restrict__ value,
        const float* __restrict__ mask,
        const float* __restrict__ attw) {
    int warp = threadIdx.x >> 5, lane = threadIdx.x & 31;
    int row0 = blockIdx.x * 32 + warp * 4;   // global row = b*N + n

    float4 wf = ((const float4*)attw)[lane];
    float4 wu = ((const float4*)(attw + Ddim))[lane];

    float m[4]; float4 v[4];
    #pragma unroll
    for (int k = 0; k < 4; k++) m[k] = mask[row0 + k];
    #pragma unroll
    for (int k = 0; k < 4; k++) {
        if (m[k] != 0.0f)
            v[k] = ((const float4*)value)[(size_t)(row0 + k) * 32 + lane];
        else
            v[k] = make_float4(0.f, 0.f, 0.f, 0.f);
    }
    #pragma unroll
    for (int k = 0; k < 4; k++) {
        float sf = v[k].x*wf.x + v[k].y*wf.y + v[k].z*wf.z + v[k].w*wf.w;
        float sg = v[k].x*wu.x + v[k].y*wu.y + v[k].z*wu.z + v[k].w*wu.w;
        // combined reduce: lanes<16 carry f, lanes>=16 carry g
        float a = sf + __shfl_xor_sync(0xffffffffu, sf, 16);
        float c = sg + __shfl_xor_sync(0xffffffffu, sg, 16);
        float s = (lane < 16) ? a : c;
        #pragma unroll
        for (int off = 8; off; off >>= 1)
            s += __shfl_xor_sync(0xffffffffu, s, off);
        if (lane == 0)  g_f[row0 + k] = s;
        if (lane == 16) g_g[row0 + k] = s;
    }
}

// ============================================================
// Scalars for hops 0 AND 1 (one block per b, 256 threads):
//   ub0 = relu(W e1 + b); sc0 = e1.wu + c
//   M0, inv_denom0; S_g = sum w_n g_n  =>  sc1 = ub0.wu + S_g*inv0 + c
//   M1, inv_denom1.  Also zeroes o0/o1.
// ============================================================
__global__ __launch_bounds__(256) void k_scal0(
        const float* __restrict__ e1,
        const float* __restrict__ lw, const float* __restrict__ lb,
        const float* __restrict__ attw, const float* __restrict__ attb,
        const float* __restrict__ mask) {
    int b = blockIdx.x, t = threadIdx.x;
    __shared__ float ush[Ddim];
    __shared__ float red[256];

    if (t < Ddim) ush[t] = e1[b * Ddim + t];
    __syncthreads();

    float ub0v = 0.0f;
    if (t < Ddim) {
        float acc = lb[t];
        const float* wr = lw + t * Ddim;
        #pragma unroll 8
        for (int k = 0; k < Ddim; k++) acc = fmaf(ush[k], __ldg(wr + k), acc);
        ub0v = fmaxf(acc, 0.0f);
        g_ub0[b * Ddim + t] = ub0v;
        g_o0[b * Ddim + t] = 0.0f;
        g_o1[b * Ddim + t] = 0.0f;
    }
    float c = attb[0];
    float sc0 = blk_sum(t < Ddim ? ush[t] * attw[Ddim + t] : 0.0f, red, t) + c;

    float mx = -1e30f;
    for (int n = t; n < Ndim; n += 256) mx = fmaxf(mx, g_f[b * Ndim + n]);
    float maxf = blk_max(mx, red, t);
    float M0 = fmaxf(maxf + sc0, 0.0f);

    float d0 = 0.0f, sg = 0.0f;
    for (int n = t; n < Ndim; n += 256) {
        float m = mask[b * Ndim + n];
        if (m != 0.0f) {
            float e = __expf(fmaxf(g_f[b * Ndim + n] + sc0, 0.0f) - M0);
            d0 += e;
            sg = fmaf(e, g_g[b * Ndim + n], sg);
        }
    }
    d0 = blk_sum(d0, red, t);
    sg = blk_sum(sg, red, t);
    float inv0 = 1.0f / (d0 + 1e-5f);

    float ubwu = blk_sum(t < Ddim ? ub0v * attw[Ddim + t] : 0.0f, red, t);
    float sc1 = ubwu + sg * inv0 + c;
    float M1 = fmaxf(maxf + sc1, 0.0f);

    float d1 = 0.0f;
    for (int n = t; n < Ndim; n += 256) {
        float m = mask[b * Ndim + n];
        if (m != 0.0f)
            d1 += __expf(fmaxf(g_f[b * Ndim + n] + sc1, 0.0f) - M1);
    }
    d1 = blk_sum(d1, red, t);

    if (t == 0) {
        float* s = &g_scal[b * 16];
        s[0] = sc0; s[1] = M0; s[2] = inv0;
        s[3] = sc1; s[4] = M1; s[5] = 1.0f / (d1 + 1e-5f);
        s[9] = maxf;
    }
}

// ============================================================
// Dual big pass: o0 += sum w0*v, o1 += sum w1*v from ONE read.
// Warp-aggregated compaction of nonzero rows -> branch-free
// float4 loop, 4 LDG.128 in flight per warp.
// ============================================================
__global__ __launch_bounds__(256) void k_attn2(
        const float* __restrict__ value,
        const float* __restrict__ mask) {
    int b = blockIdx.x, n0 = blockIdx.y * CH, t = threadIdx.x;
    int warp = t >> 5, lane = t & 31;

    __shared__ float wA[CH], wB[CH];
    __shared__ int rowl[CH];
    __shared__ int cnt;
    __shared__ float4 part[8][32];
    if (t == 0) cnt = 0;
    __syncthreads();

    const float* s = &g_scal[b * 16];
    float sc0 = s[0], M0 = s[1], inv0 = s[2];
    float sc1 = s[3], M1 = s[4], inv1 = s[5];

    {   // weight compute + warp-aggregated compaction
        int n = n0 + t;
        float m = mask[b * Ndim + n];
        unsigned bal = __ballot_sync(0xffffffffu, m != 0.0f);
        float w0 = 0.f, w1 = 0.f;
        if (m != 0.0f) {
            float f = g_f[b * Ndim + n];
            w0 = __expf(fmaxf(f + sc0, 0.0f) - M0) * inv0;
            w1 = __expf(fmaxf(f + sc1, 0.0f) - M1) * inv1;
        }
        int base = 0;
        if (lane == 0) base = atomicAdd(&cnt, __popc(bal));
        base = __shfl_sync(0xffffffffu, base, 0);
        if (m != 0.0f) {
            int idx = base + __popc(bal & ((1u << lane) - 1u));
            rowl[idx] = t; wA[idx] = w0; wB[idx] = w1;
        }
    }
    __syncthreads();
    int C = cnt;

    float4 a0 = make_float4(0.f,0.f,0.f,0.f);
    float4 a1 = make_float4(0.f,0.f,0.f,0.f);
    const float4* vp = (const float4*)value + ((size_t)b * Ndim + n0) * 32;

    int j = warp;
    for (; j + 32 <= C; j += 32) {
        int r0 = rowl[j], r1 = rowl[j+8], r2 = rowl[j+16], r3 = rowl[j+24];
        float4 v0 = vp[r0*32 + lane], v1 = vp[r1*32 + lane];
        float4 v2 = vp[r2*32 + lane], v3 = vp[r3*32 + lane];
        float p0 = wA[j], q0 = wB[j], p1 = wA[j+8],  q1 = wB[j+8];
        float p2 = wA[j+16], q2 = wB[j+16], p3 = wA[j+24], q3 = wB[j+24];
        a0.x = fmaf(p0,v0.x,a0.x); a0.y = fmaf(p0,v0.y,a0.y); a0.z = fmaf(p0,v0.z,a0.z); a0.w = fmaf(p0,v0.w,a0.w);
        a1.x = fmaf(q0,v0.x,a1.x); a1.y = fmaf(q0,v0.y,a1.y); a1.z = fmaf(q0,v0.z,a1.z); a1.w = fmaf(q0,v0.w,a1.w);
        a0.x = fmaf(p1,v1.x,a0.x); a0.y = fmaf(p1,v1.y,a0.y); a0.z = fmaf(p1,v1.z,a0.z); a0.w = fmaf(p1,v1.w,a0.w);
        a1.x = fmaf(q1,v1.x,a1.x); a1.y = fmaf(q1,v1.y,a1.y); a1.z = fmaf(q1,v1.z,a1.z); a1.w = fmaf(q1,v1.w,a1.w);
        a0.x = fmaf(p2,v2.x,a0.x); a0.y = fmaf(p2,v2.y,a0.y); a0.z = fmaf(p2,v2.z,a0.z); a0.w = fmaf(p2,v2.w,a0.w);
        a1.x = fmaf(q2,v2.x,a1.x); a1.y = fmaf(q2,v2.y,a1.y); a1.z = fmaf(q2,v2.z,a1.z); a1.w = fmaf(q2,v2.w,a1.w);
        a0.x = fmaf(p3,v3.x,a0.x); a0.y = fmaf(p3,v3.y,a0.y); a0.z = fmaf(p3,v3.z,a0.z); a0.w = fmaf(p3,v3.w,a0.w);
        a1.x = fmaf(q3,v3.x,a1.x); a1.y = fmaf(q3,v3.y,a1.y); a1.z = fmaf(q3,v3.z,a1.z); a1.w = fmaf(q3,v3.w,a1.w);
    }
    for (; j < C; j += 8) {
        int r = rowl[j];
        float4 v = vp[r*32 + lane];
        float p = wA[j], q = wB[j];
        a0.x = fmaf(p,v.x,a0.x); a0.y = fmaf(p,v.y,a0.y); a0.z = fmaf(p,v.z,a0.z); a0.w = fmaf(p,v.w,a0.w);
        a1.x = fmaf(q,v.x,a1.x); a1.y = fmaf(q,v.y,a1.y); a1.z = fmaf(q,v.z,a1.z); a1.w = fmaf(q,v.w,a1.w);
    }

    // cross-warp reduce + atomic accumulate
    part[warp][lane] = a0; __syncthreads();
    if (warp == 0) {
        float4 r = part[0][lane];
        #pragma unroll
        for (int w = 1; w < 8; w++) {
            float4 p = part[w][lane];
            r.x += p.x; r.y += p.y; r.z += p.z; r.w += p.w;
        }
        float* o = &g_o0[b * Ddim + lane * 4];
        atomicAdd(o+0, r.x); atomicAdd(o+1, r.y);
        atomicAdd(o+2, r.z); atomicAdd(o+3, r.w);
    }
    __syncthreads();
    part[warp][lane] = a1; __syncthreads();
    if (warp == 0) {
        float4 r = part[0][lane];
        #pragma unroll
        for (int w = 1; w < 8; w++) {
            float4 p = part[w][lane];
            r.x += p.x; r.y += p.y; r.z += p.z; r.w += p.w;
        }
        float* o = &g_o1[b * Ddim + lane * 4];
        atomicAdd(o+0, r.x); atomicAdd(o+1, r.y);
        atomicAdd(o+2, r.z); atomicAdd(o+3, r.w);
    }
}

// ============================================================
// Hop-2 scalars + final GEMVs:
//   u1 = ub0+o0; ub1 = relu(W u1+b); u2 = ub1+o1; ub2 = relu(W u2+b)
//   out = ub2 (o2 added atomically by k_attn1); sc2/M2/inv2.
// ============================================================
__global__ __launch_bounds__(256) void k_scal1(
        const float* __restrict__ lw, const float* __restrict__ lb,
        const float* __restrict__ attw, const float* __restrict__ attb,
        const float* __restrict__ mask, float* __restrict__ out) {
    int b = blockIdx.x, t = threadIdx.x;
    __shared__ float u1[Ddim], u2[Ddim];
    __shared__ float red[256];

    if (t < Ddim) u1[t] = g_ub0[b * Ddim + t] + g_o0[b * Ddim + t];
    __syncthreads();
    if (t < Ddim) {
        float acc = lb[t];
        const float* wr = lw + t * Ddim;
        #pragma unroll 8
        for (int k = 0; k < Ddim; k++) acc = fmaf(u1[k], __ldg(wr + k), acc);
        u2[t] = fmaxf(acc, 0.0f) + g_o1[b * Ddim + t];
    }
    __syncthreads();
    if (t < Ddim) {
        float acc = lb[t];
        const float* wr = lw + t * Ddim;
        #pragma unroll 8
        for (int k = 0; k < Ddim; k++) acc = fmaf(u2[k], __ldg(wr + k), acc);
        out[b * Ddim + t] = fmaxf(acc, 0.0f);   // ub2; o2 added by k_attn1
    }
    float c = attb[0];
    float sc2 = blk_sum(t < Ddim ? u2[t] * attw[Ddim + t] : 0.0f, red, t) + c;
    float maxf = g_scal[b * 16 + 9];
    float M2 = fmaxf(maxf + sc2, 0.0f);

    float d2 = 0.0f;
    for (int n = t; n < Ndim; n += 256) {
        float m = mask[b * Ndim + n];
        if (m != 0.0f)
            d2 += __expf(fmaxf(g_f[b * Ndim + n] + sc2, 0.0f) - M2);
    }
    d2 = blk_sum(d2, red, t);
    if (t == 0) {
        float* s = &g_scal[b * 16];
        s[6] = sc2; s[7] = M2; s[8] = 1.0f / (d2 + 1e-5f);
    }
}

// ============================================================
// Single big pass: out += sum w2 * v (hop 2)
// ============================================================
__global__ __launch_bounds__(256) void k_attn1(
        const float* __restrict__ value,
        const float* __restrict__ mask,
        float* __restrict__ out) {
    int b = blockIdx.x, n0 = blockIdx.y * CH, t = threadIdx.x;
    int warp = t >> 5, lane = t & 31;

    __shared__ float wA[CH];
    __shared__ int rowl[CH];
    __shared__ int cnt;
    __shared__ float4 part[8][32];
    if (t == 0) cnt = 0;
    __syncthreads();

    const float* s = &g_scal[b * 16];
    float sc2 = s[6], M2 = s[7], inv2 = s[8];

    {
        int n = n0 + t;
        float m = mask[b * Ndim + n];
        unsigned bal = __ballot_sync(0xffffffffu, m != 0.0f);
        float w = 0.f;
        if (m != 0.0f) {
            float f = g_f[b * Ndim + n];
            w = __expf(fmaxf(f + sc2, 0.0f) - M2) * inv2;
        }
        int base = 0;
        if (lane == 0) base = atomicAdd(&cnt, __popc(bal));
        base = __shfl_sync(0xffffffffu, base, 0);
        if (m != 0.0f) {
            int idx = base + __popc(bal & ((1u << lane) - 1u));
            rowl[idx] = t; wA[idx] = w;
        }
    }
    __syncthreads();
    int C = cnt;

    float4 a0 = make_float4(0.f,0.f,0.f,0.f);
    const float4* vp = (const float4*)value + ((size_t)b * Ndim + n0) * 32;

    int j = warp;
    for (; j + 32 <= C; j += 32) {
        int r0 = rowl[j], r1 = rowl[j+8], r2 = rowl[j+16], r3 = rowl[j+24];
        float4 v0 = vp[r0*32 + lane], v1 = vp[r1*32 + lane];
        float4 v2 = vp[r2*32 + lane], v3 = vp[r3*32 + lane];
        float p0 = wA[j], p1 = wA[j+8], p2 = wA[j+16], p3 = wA[j+24];
        a0.x = fmaf(p0,v0.x,a0.x); a0.y = fmaf(p0,v0.y,a0.y); a0.z = fmaf(p0,v0.z,a0.z); a0.w = fmaf(p0,v0.w,a0.w);
        a0.x = fmaf(p1,v1.x,a0.x); a0.y = fmaf(p1,v1.y,a0.y); a0.z = fmaf(p1,v1.z,a0.z); a0.w = fmaf(p1,v1.w,a0.w);
        a0.x = fmaf(p2,v2.x,a0.x); a0.y = fmaf(p2,v2.y,a0.y); a0.z = fmaf(p2,v2.z,a0.z); a0.w = fmaf(p2,v2.w,a0.w);
        a0.x = fmaf(p3,v3.x,a0.x); a0.y = fmaf(p3,v3.y,a0.y); a0.z = fmaf(p3,v3.z,a0.z); a0.w = fmaf(p3,v3.w,a0.w);
    }
    for (; j < C; j += 8) {
        int r = rowl[j];
        float4 v = vp[r*32 + lane];
        float p = wA[j];
        a0.x = fmaf(p,v.x,a0.x); a0.y = fmaf(p,v.y,a0.y); a0.z = fmaf(p,v.z,a0.z); a0.w = fmaf(p,v.w,a0.w);
    }

    part[warp][lane] = a0; __syncthreads();
    if (warp == 0) {
        float4 r = part[0][lane];
        #pragma unroll
        for (int w = 1; w < 8; w++) {
            float4 p = part[w][lane];
            r.x += p.x; r.y += p.y; r.z += p.z; r.w += p.w;
        }
        float* o = &out[b * Ddim + lane * 4];
        atomicAdd(o+0, r.x); atomicAdd(o+1, r.y);
        atomicAdd(o+2, r.z); atomicAdd(o+3, r.w);
    }
}

// ============================================================
extern "C" void kernel_launch(void* const* d_in, const int* in_sizes, int n_in,
                              void* d_out, int out_size) {
    const float* e1    = (const float*)d_in[0];
    // d_in[1] rel_embeded, d_in[2] nei_embeded_key: unused by reference
    const float* value = (const float*)d_in[3];
    const float* mask  = (const float*)d_in[4];
    const float* lw    = (const float*)d_in[5];
    const float* lb    = (const float*)d_in[6];
    const float* aw    = (const float*)d_in[7];
    const float* ab    = (const float*)d_in[8];
    float* out = (float*)d_out;

    k_pass1<<<(Bdim * Ndim) / 32, 256>>>(value, mask, aw);
    k_scal0<<<Bdim, 256>>>(e1, lw, lb, aw, ab, mask);
    dim3 g2(Bdim, Ndim / CH);
    k_attn2<<<g2, 256>>>(value, mask);
    k_scal1<<<Bdim, 256>>>(lw, lb, aw, ab, mask, out);
    k_attn1<<<g2, 256>>>(value, mask, out);
}

// round 4
// speedup vs baseline: 2.4926x; 1.1632x over previous
#include <cuda_runtime.h>

#define Bdim 128
#define Ndim 2048
#define Ddim 128
#define CH 256          // rows per k_attn block

// ---- scratch (allocation-free device globals) ----
__device__ float g_f[Bdim * Ndim];    // masked f_n = mask * (v . w_f)
__device__ float g_g[Bdim * Ndim];    // masked g_n = mask * (v . w_u)
__device__ float g_wt[Ddim * Ddim];   // linfc_w transposed: WT[k][t] = W[t][k]
__device__ float g_ub0[Bdim * Ddim];  // relu(W e1 + b)
__device__ float g_o0[Bdim * Ddim];
__device__ float g_o1[Bdim * Ddim];
__device__ float g_scal[Bdim * 16];   // [0]sc0 [1]M0 [2]inv0 [3]sc1 [4]M1 [5]inv1
                                      // [6]sc2 [7]M2 [8]inv2 [9]maxf

// ---------- block reduction helpers (256 threads) ----------
__device__ __forceinline__ float blk_sum(float v, float* red, int t) {
    red[t] = v; __syncthreads();
    #pragma unroll
    for (int off = 128; off; off >>= 1) {
        if (t < off) red[t] += red[t + off];
        __syncthreads();
    }
    float r = red[0]; __syncthreads();
    return r;
}
__device__ __forceinline__ float blk_max(float v, float* red, int t) {
    red[t] = v; __syncthreads();
    #pragma unroll
    for (int off = 128; off; off >>= 1) {
        if (t < off) red[t] = fmaxf(red[t], red[t + off]);
        __syncthreads();
    }
    float r = red[0]; __syncthreads();
    return r;
}

// Coalesced GEMV from transposed weights: out[t] = b[t] + sum_k u[k]*WT[k*128+t]
// (lane-coalesced LDG.32, 2 accumulators to halve the fma dep chain)
__device__ __forceinline__ float gemv_wt(const float* __restrict__ ush,
                                         float bias, int t) {
    float a0 = bias, a1 = 0.0f;
    #pragma unroll 8
    for (int k = 0; k < Ddim; k += 2) {
        a0 = fmaf(ush[k],     g_wt[k * Ddim + t],       a0);
        a1 = fmaf(ush[k + 1], g_wt[(k + 1) * Ddim + t], a1);
    }
    return a0 + a1;
}

// ============================================================
// One-time transpose of linfc_w (64 KB)
// ============================================================
__global__ __launch_bounds__(256) void k_wt(const float* __restrict__ lw) {
    int i = blockIdx.x * 256 + threadIdx.x;     // i = t*128 + k
    int t = i >> 7, k = i & 127;
    g_wt[k * Ddim + t] = __ldg(lw + i);
}

// ============================================================
// Pass 1 (once): f = mask*(v.w_f), g = mask*(v.w_u)
// 8 warps/block, 4 rows/warp (4 LDG.128 in flight), combined
// f/g butterfly reduction.
// ============================================================
__global__ __launch_bounds__(256) void k_pass1(
        const float* __restrict__ value,
        const float* __restrict__ mask,
        const float* __restrict__ attw) {
    int warp = threadIdx.x >> 5, lane = threadIdx.x & 31;
    int row0 = blockIdx.x * 32 + warp * 4;   // global row = b*N + n

    float4 wf = ((const float4*)attw)[lane];
    float4 wu = ((const float4*)(attw + Ddim))[lane];

    float m[4]; float4 v[4];
    #pragma unroll
    for (int k = 0; k < 4; k++) m[k] = mask[row0 + k];
    #pragma unroll
    for (int k = 0; k < 4; k++) {
        if (m[k] != 0.0f)
            v[k] = ((const float4*)value)[(size_t)(row0 + k) * 32 + lane];
        else
            v[k] = make_float4(0.f, 0.f, 0.f, 0.f);
    }
    #pragma unroll
    for (int k = 0; k < 4; k++) {
        float sf = v[k].x*wf.x + v[k].y*wf.y + v[k].z*wf.z + v[k].w*wf.w;
        float sg = v[k].x*wu.x + v[k].y*wu.y + v[k].z*wu.z + v[k].w*wu.w;
        float a = sf + __shfl_xor_sync(0xffffffffu, sf, 16);
        float c = sg + __shfl_xor_sync(0xffffffffu, sg, 16);
        float s = (lane < 16) ? a : c;
        #pragma unroll
        for (int off = 8; off; off >>= 1)
            s += __shfl_xor_sync(0xffffffffu, s, off);
        if (lane == 0)  g_f[row0 + k] = s;
        if (lane == 16) g_g[row0 + k] = s;
    }
}

// ============================================================
// Scalars for hops 0 AND 1 (one block per b, 256 threads)
// ============================================================
__global__ __launch_bounds__(256) void k_scal0(
        const float* __restrict__ e1,
        const float* __restrict__ lb,
        const float* __restrict__ attw, const float* __restrict__ attb,
        const float* __restrict__ mask) {
    int b = blockIdx.x, t = threadIdx.x;
    __shared__ float ush[Ddim];
    __shared__ float red[256];

    if (t < Ddim) ush[t] = e1[b * Ddim + t];
    __syncthreads();

    float ub0v = 0.0f;
    if (t < Ddim) {
        ub0v = fmaxf(gemv_wt(ush, lb[t], t), 0.0f);
        g_ub0[b * Ddim + t] = ub0v;
        g_o0[b * Ddim + t] = 0.0f;
        g_o1[b * Ddim + t] = 0.0f;
    }
    float c = attb[0];
    float sc0 = blk_sum(t < Ddim ? ush[t] * attw[Ddim + t] : 0.0f, red, t) + c;

    float mx = -1e30f;
    for (int n = t; n < Ndim; n += 256) mx = fmaxf(mx, g_f[b * Ndim + n]);
    float maxf = blk_max(mx, red, t);
    float M0 = fmaxf(maxf + sc0, 0.0f);

    float d0 = 0.0f, sg = 0.0f;
    for (int n = t; n < Ndim; n += 256) {
        float m = mask[b * Ndim + n];
        if (m != 0.0f) {
            float e = __expf(fmaxf(g_f[b * Ndim + n] + sc0, 0.0f) - M0);
            d0 += e;
            sg = fmaf(e, g_g[b * Ndim + n], sg);
        }
    }
    d0 = blk_sum(d0, red, t);
    sg = blk_sum(sg, red, t);
    float inv0 = 1.0f / (d0 + 1e-5f);

    float ubwu = blk_sum(t < Ddim ? ub0v * attw[Ddim + t] : 0.0f, red, t);
    float sc1 = ubwu + sg * inv0 + c;
    float M1 = fmaxf(maxf + sc1, 0.0f);

    float d1 = 0.0f;
    for (int n = t; n < Ndim; n += 256) {
        float m = mask[b * Ndim + n];
        if (m != 0.0f)
            d1 += __expf(fmaxf(g_f[b * Ndim + n] + sc1, 0.0f) - M1);
    }
    d1 = blk_sum(d1, red, t);

    if (t == 0) {
        float* s = &g_scal[b * 16];
        s[0] = sc0; s[1] = M0; s[2] = inv0;
        s[3] = sc1; s[4] = M1; s[5] = 1.0f / (d1 + 1e-5f);
        s[9] = maxf;
    }
}

// ============================================================
// Dual big pass: o0 += sum w0*v, o1 += sum w1*v from ONE read.
// Warp-aggregated compaction -> branch-free float4 loop.
// ============================================================
__global__ __launch_bounds__(256) void k_attn2(
        const float* __restrict__ value,
        const float* __restrict__ mask) {
    int b = blockIdx.x, n0 = blockIdx.y * CH, t = threadIdx.x;
    int warp = t >> 5, lane = t & 31;

    __shared__ float wA[CH], wB[CH];
    __shared__ int rowl[CH];
    __shared__ int cnt;
    __shared__ float4 part[8][32];
    if (t == 0) cnt = 0;
    __syncthreads();

    const float* s = &g_scal[b * 16];
    float sc0 = s[0], M0 = s[1], inv0 = s[2];
    float sc1 = s[3], M1 = s[4], inv1 = s[5];

    {   // weight compute + warp-aggregated compaction
        int n = n0 + t;
        float m = mask[b * Ndim + n];
        unsigned bal = __ballot_sync(0xffffffffu, m != 0.0f);
        float w0 = 0.f, w1 = 0.f;
        if (m != 0.0f) {
            float f = g_f[b * Ndim + n];
            w0 = __expf(fmaxf(f + sc0, 0.0f) - M0) * inv0;
            w1 = __expf(fmaxf(f + sc1, 0.0f) - M1) * inv1;
        }
        int base = 0;
        if (lane == 0) base = atomicAdd(&cnt, __popc(bal));
        base = __shfl_sync(0xffffffffu, base, 0);
        if (m != 0.0f) {
            int idx = base + __popc(bal & ((1u << lane) - 1u));
            rowl[idx] = t; wA[idx] = w0; wB[idx] = w1;
        }
    }
    __syncthreads();
    int C = cnt;

    float4 a0 = make_float4(0.f,0.f,0.f,0.f);
    float4 a1 = make_float4(0.f,0.f,0.f,0.f);
    const float4* vp = (const float4*)value + ((size_t)b * Ndim + n0) * 32;

    int j = warp;
    for (; j + 32 <= C; j += 32) {
        int r0 = rowl[j], r1 = rowl[j+8], r2 = rowl[j+16], r3 = rowl[j+24];
        float4 v0 = vp[r0*32 + lane], v1 = vp[r1*32 + lane];
        float4 v2 = vp[r2*32 + lane], v3 = vp[r3*32 + lane];
        float p0 = wA[j], q0 = wB[j], p1 = wA[j+8],  q1 = wB[j+8];
        float p2 = wA[j+16], q2 = wB[j+16], p3 = wA[j+24], q3 = wB[j+24];
        a0.x = fmaf(p0,v0.x,a0.x); a0.y = fmaf(p0,v0.y,a0.y); a0.z = fmaf(p0,v0.z,a0.z); a0.w = fmaf(p0,v0.w,a0.w);
        a1.x = fmaf(q0,v0.x,a1.x); a1.y = fmaf(q0,v0.y,a1.y); a1.z = fmaf(q0,v0.z,a1.z); a1.w = fmaf(q0,v0.w,a1.w);
        a0.x = fmaf(p1,v1.x,a0.x); a0.y = fmaf(p1,v1.y,a0.y); a0.z = fmaf(p1,v1.z,a0.z); a0.w = fmaf(p1,v1.w,a0.w);
        a1.x = fmaf(q1,v1.x,a1.x); a1.y = fmaf(q1,v1.y,a1.y); a1.z = fmaf(q1,v1.z,a1.z); a1.w = fmaf(q1,v1.w,a1.w);
        a0.x = fmaf(p2,v2.x,a0.x); a0.y = fmaf(p2,v2.y,a0.y); a0.z = fmaf(p2,v2.z,a0.z); a0.w = fmaf(p2,v2.w,a0.w);
        a1.x = fmaf(q2,v2.x,a1.x); a1.y = fmaf(q2,v2.y,a1.y); a1.z = fmaf(q2,v2.z,a1.z); a1.w = fmaf(q2,v2.w,a1.w);
        a0.x = fmaf(p3,v3.x,a0.x); a0.y = fmaf(p3,v3.y,a0.y); a0.z = fmaf(p3,v3.z,a0.z); a0.w = fmaf(p3,v3.w,a0.w);
        a1.x = fmaf(q3,v3.x,a1.x); a1.y = fmaf(q3,v3.y,a1.y); a1.z = fmaf(q3,v3.z,a1.z); a1.w = fmaf(q3,v3.w,a1.w);
    }
    for (; j < C; j += 8) {
        int r = rowl[j];
        float4 v = vp[r*32 + lane];
        float p = wA[j], q = wB[j];
        a0.x = fmaf(p,v.x,a0.x); a0.y = fmaf(p,v.y,a0.y); a0.z = fmaf(p,v.z,a0.z); a0.w = fmaf(p,v.w,a0.w);
        a1.x = fmaf(q,v.x,a1.x); a1.y = fmaf(q,v.y,a1.y); a1.z = fmaf(q,v.z,a1.z); a1.w = fmaf(q,v.w,a1.w);
    }

    part[warp][lane] = a0; __syncthreads();
    if (warp == 0) {
        float4 r = part[0][lane];
        #pragma unroll
        for (int w = 1; w < 8; w++) {
            float4 p = part[w][lane];
            r.x += p.x; r.y += p.y; r.z += p.z; r.w += p.w;
        }
        float* o = &g_o0[b * Ddim + lane * 4];
        atomicAdd(o+0, r.x); atomicAdd(o+1, r.y);
        atomicAdd(o+2, r.z); atomicAdd(o+3, r.w);
    }
    __syncthreads();
    part[warp][lane] = a1; __syncthreads();
    if (warp == 0) {
        float4 r = part[0][lane];
        #pragma unroll
        for (int w = 1; w < 8; w++) {
            float4 p = part[w][lane];
            r.x += p.x; r.y += p.y; r.z += p.z; r.w += p.w;
        }
        float* o = &g_o1[b * Ddim + lane * 4];
        atomicAdd(o+0, r.x); atomicAdd(o+1, r.y);
        atomicAdd(o+2, r.z); atomicAdd(o+3, r.w);
    }
}

// ============================================================
// Hop-2 scalars + final GEMVs (coalesced via g_wt)
// ============================================================
__global__ __launch_bounds__(256) void k_scal1(
        const float* __restrict__ lb,
        const float* __restrict__ attw, const float* __restrict__ attb,
        const float* __restrict__ mask, float* __restrict__ out) {
    int b = blockIdx.x, t = threadIdx.x;
    __shared__ float u1[Ddim], u2[Ddim];
    __shared__ float red[256];

    if (t < Ddim) u1[t] = g_ub0[b * Ddim + t] + g_o0[b * Ddim + t];
    __syncthreads();
    if (t < Ddim)
        u2[t] = fmaxf(gemv_wt(u1, lb[t], t), 0.0f) + g_o1[b * Ddim + t];
    __syncthreads();
    if (t < Ddim)
        out[b * Ddim + t] = fmaxf(gemv_wt(u2, lb[t], t), 0.0f); // ub2; o2 added by k_attn1

    float c = attb[0];
    float sc2 = blk_sum(t < Ddim ? u2[t] * attw[Ddim + t] : 0.0f, red, t) + c;
    float maxf = g_scal[b * 16 + 9];
    float M2 = fmaxf(maxf + sc2, 0.0f);

    float d2 = 0.0f;
    for (int n = t; n < Ndim; n += 256) {
        float m = mask[b * Ndim + n];
        if (m != 0.0f)
            d2 += __expf(fmaxf(g_f[b * Ndim + n] + sc2, 0.0f) - M2);
    }
    d2 = blk_sum(d2, red, t);
    if (t == 0) {
        float* s = &g_scal[b * 16];
        s[6] = sc2; s[7] = M2; s[8] = 1.0f / (d2 + 1e-5f);
    }
}

// ============================================================
// Single big pass: out += sum w2 * v (hop 2)
// ============================================================
__global__ __launch_bounds__(256) void k_attn1(
        const float* __restrict__ value,
        const float* __restrict__ mask,
        float* __restrict__ out) {
    int b = blockIdx.x, n0 = blockIdx.y * CH, t = threadIdx.x;
    int warp = t >> 5, lane = t & 31;

    __shared__ float wA[CH];
    __shared__ int rowl[CH];
    __shared__ int cnt;
    __shared__ float4 part[8][32];
    if (t == 0) cnt = 0;
    __syncthreads();

    const float* s = &g_scal[b * 16];
    float sc2 = s[6], M2 = s[7], inv2 = s[8];

    {
        int n = n0 + t;
        float m = mask[b * Ndim + n];
        unsigned bal = __ballot_sync(0xffffffffu, m != 0.0f);
        float w = 0.f;
        if (m != 0.0f) {
            float f = g_f[b * Ndim + n];
            w = __expf(fmaxf(f + sc2, 0.0f) - M2) * inv2;
        }
        int base = 0;
        if (lane == 0) base = atomicAdd(&cnt, __popc(bal));
        base = __shfl_sync(0xffffffffu, base, 0);
        if (m != 0.0f) {
            int idx = base + __popc(bal & ((1u << lane) - 1u));
            rowl[idx] = t; wA[idx] = w;
        }
    }
    __syncthreads();
    int C = cnt;

    float4 a0 = make_float4(0.f,0.f,0.f,0.f);
    const float4* vp = (const float4*)value + ((size_t)b * Ndim + n0) * 32;

    int j = warp;
    for (; j + 32 <= C; j += 32) {
        int r0 = rowl[j], r1 = rowl[j+8], r2 = rowl[j+16], r3 = rowl[j+24];
        float4 v0 = vp[r0*32 + lane], v1 = vp[r1*32 + lane];
        float4 v2 = vp[r2*32 + lane], v3 = vp[r3*32 + lane];
        float p0 = wA[j], p1 = wA[j+8], p2 = wA[j+16], p3 = wA[j+24];
        a0.x = fmaf(p0,v0.x,a0.x); a0.y = fmaf(p0,v0.y,a0.y); a0.z = fmaf(p0,v0.z,a0.z); a0.w = fmaf(p0,v0.w,a0.w);
        a0.x = fmaf(p1,v1.x,a0.x); a0.y = fmaf(p1,v1.y,a0.y); a0.z = fmaf(p1,v1.z,a0.z); a0.w = fmaf(p1,v1.w,a0.w);
        a0.x = fmaf(p2,v2.x,a0.x); a0.y = fmaf(p2,v2.y,a0.y); a0.z = fmaf(p2,v2.z,a0.z); a0.w = fmaf(p2,v2.w,a0.w);
        a0.x = fmaf(p3,v3.x,a0.x); a0.y = fmaf(p3,v3.y,a0.y); a0.z = fmaf(p3,v3.z,a0.z); a0.w = fmaf(p3,v3.w,a0.w);
    }
    for (; j < C; j += 8) {
        int r = rowl[j];
        float4 v = vp[r*32 + lane];
        float p = wA[j];
        a0.x = fmaf(p,v.x,a0.x); a0.y = fmaf(p,v.y,a0.y); a0.z = fmaf(p,v.z,a0.z); a0.w = fmaf(p,v.w,a0.w);
    }

    part[warp][lane] = a0; __syncthreads();
    if (warp == 0) {
        float4 r = part[0][lane];
        #pragma unroll
        for (int w = 1; w < 8; w++) {
            float4 p = part[w][lane];
            r.x += p.x; r.y += p.y; r.z += p.z; r.w += p.w;
        }
        float* o = &out[b * Ddim + lane * 4];
        atomicAdd(o+0, r.x); atomicAdd(o+1, r.y);
        atomicAdd(o+2, r.z); atomicAdd(o+3, r.w);
    }
}

// ============================================================
extern "C" void kernel_launch(void* const* d_in, const int* in_sizes, int n_in,
                              void* d_out, int out_size) {
    const float* e1    = (const float*)d_in[0];
    // d_in[1] rel_embeded, d_in[2] nei_embeded_key: unused by reference
    const float* value = (const float*)d_in[3];
    const float* mask  = (const float*)d_in[4];
    const float* lw    = (const float*)d_in[5];
    const float* lb    = (const float*)d_in[6];
    const float* aw    = (const float*)d_in[7];
    const float* ab    = (const float*)d_in[8];
    float* out = (float*)d_out;

    k_wt<<<(Ddim * Ddim) / 256, 256>>>(lw);
    k_pass1<<<(Bdim * Ndim) / 32, 256>>>(value, mask, aw);
    k_scal0<<<Bdim, 256>>>(e1, lb, aw, ab, mask);
    dim3 g2(Bdim, Ndim / CH);
    k_attn2<<<g2, 256>>>(value, mask);
    k_scal1<<<Bdim, 256>>>(lb, aw, ab, mask, out);
    k_attn1<<<g2, 256>>>(value, mask, out);
}